// round 4
// baseline (speedup 1.0000x reference)
#include <cuda_runtime.h>
#include <cstdint>
#include <cstddef>

#define N_TOKENS 8192
#define HDIM     1024
#define NHEADS   16
#define SLOTS    16
#define SD       32
#define HD       64
#define FULLMASK 0xffffffffu

typedef unsigned long long u64;

__device__ float4 g_act4[N_TOKENS * NHEADS];
__device__ float  g_WaT[48 * HDIM];                      // WaT[col][k]
__device__ float4 g_kv4[(size_t)N_TOKENS * NHEADS * 8];  // kv [tok][head][32] (16MB)
__device__ float4 g_mem4[(size_t)N_TOKENS * NHEADS * 8]; // mem [tok][head][32] (16MB)

// ---------------------- f32x2 / float4 helpers ----------------------
__device__ __forceinline__ u64 pack2(float x, float y) {
    u64 r; asm("mov.b64 %0,{%1,%2};" : "=l"(r) : "f"(x), "f"(y)); return r;
}
__device__ __forceinline__ void fma2(u64& d, u64 a, u64 b) {
    asm("fma.rn.f32x2 %0,%1,%2,%0;" : "+l"(d) : "l"(a), "l"(b));
}
__device__ __forceinline__ float2 unpack2(u64 v) {
    float2 r; asm("mov.b64 {%0,%1},%2;" : "=f"(r.x), "=f"(r.y) : "l"(v)); return r;
}
__device__ __forceinline__ float4 f4zero() { return make_float4(0.f, 0.f, 0.f, 0.f); }
__device__ __forceinline__ float4 f4fma(float a, float4 b, float4 c) {
    return make_float4(fmaf(a, b.x, c.x), fmaf(a, b.y, c.y),
                       fmaf(a, b.z, c.z), fmaf(a, b.w, c.w));
}
__device__ __forceinline__ float4 f4add(float4 a, float4 b) {
    return make_float4(a.x + b.x, a.y + b.y, a.z + b.z, a.w + b.w);
}
__device__ __forceinline__ float dot4(float4 a, float4 b) {
    return fmaf(a.x, b.x, fmaf(a.y, b.y, fmaf(a.z, b.z, a.w * b.w)));
}
__device__ __forceinline__ float4 f4shflxor(float4 v, int m) {
    return make_float4(__shfl_xor_sync(FULLMASK, v.x, m),
                       __shfl_xor_sync(FULLMASK, v.y, m),
                       __shfl_xor_sync(FULLMASK, v.z, m),
                       __shfl_xor_sync(FULLMASK, v.w, m));
}

// ---------------------------------------------------------------------------
// Kernel 0: transpose Wa [1024][48] -> g_WaT [48][1024]
// ---------------------------------------------------------------------------
__global__ __launch_bounds__(256) void k_waT(const float* __restrict__ Wa)
{
    const int col = blockIdx.x >> 2;
    const int k   = (blockIdx.x & 3) * 256 + threadIdx.x;
    g_WaT[col * HDIM + k] = Wa[(size_t)k * 48 + col];
}

// ---------------------------------------------------------------------------
// Kernel 1: actions = softmax_3( (hidden @ Wa + ba) / 8 ), f32x2 FMA.
// 32 tokens/block, 256 threads, thread tile 2 tok x 3 col.
// ---------------------------------------------------------------------------
__global__ __launch_bounds__(256) void k_actions(
    const float* __restrict__ hidden,
    const float* __restrict__ ba)
{
    __shared__ __align__(16) float sA[32][68];
    __shared__ __align__(16) float sWT[48][68];

    const int tid  = threadIdx.x;
    const int tg   = tid >> 4;
    const int hx   = tid & 15;
    const int tok0 = blockIdx.x * 32;
    const float4* hid4 = (const float4*)hidden;
    const float4* waT4 = (const float4*)g_WaT;

    u64 acc[2][3];
#pragma unroll
    for (int i = 0; i < 2; i++)
#pragma unroll
        for (int j = 0; j < 3; j++) acc[i][j] = 0ull;

    for (int k0 = 0; k0 < HDIM; k0 += 64) {
#pragma unroll
        for (int idx = tid; idx < 512; idx += 256) {
            int r = idx >> 4, c4 = idx & 15;
            *(float4*)&sA[r][c4 * 4] = hid4[(size_t)(tok0 + r) * 256 + (k0 >> 2) + c4];
        }
#pragma unroll
        for (int idx = tid; idx < 768; idx += 256) {
            int r = idx >> 4, c4 = idx & 15;
            *(float4*)&sWT[r][c4 * 4] = waT4[(size_t)r * 256 + (k0 >> 2) + c4];
        }
        __syncthreads();

#pragma unroll
        for (int k2 = 0; k2 < 32; k2++) {
            u64 a0 = *(const u64*)&sA[tg * 2 + 0][k2 * 2];
            u64 a1 = *(const u64*)&sA[tg * 2 + 1][k2 * 2];
            u64 w0 = *(const u64*)&sWT[hx * 3 + 0][k2 * 2];
            u64 w1 = *(const u64*)&sWT[hx * 3 + 1][k2 * 2];
            u64 w2 = *(const u64*)&sWT[hx * 3 + 2][k2 * 2];
            fma2(acc[0][0], a0, w0); fma2(acc[0][1], a0, w1); fma2(acc[0][2], a0, w2);
            fma2(acc[1][0], a1, w0); fma2(acc[1][1], a1, w1); fma2(acc[1][2], a1, w2);
        }
        __syncthreads();
    }

    const float b0 = ba[hx * 3 + 0];
    const float b1 = ba[hx * 3 + 1];
    const float b2 = ba[hx * 3 + 2];

#pragma unroll
    for (int i = 0; i < 2; i++) {
        float2 p0 = unpack2(acc[i][0]);
        float2 p1 = unpack2(acc[i][1]);
        float2 p2 = unpack2(acc[i][2]);
        float l0 = (p0.x + p0.y + b0) * 0.125f;
        float l1 = (p1.x + p1.y + b1) * 0.125f;
        float l2 = (p2.x + p2.y + b2) * 0.125f;
        float mx = fmaxf(l0, fmaxf(l1, l2));
        float e0 = __expf(l0 - mx);
        float e1 = __expf(l1 - mx);
        float e2 = __expf(l2 - mx);
        float inv = 1.f / (e0 + e1 + e2);
        g_act4[(size_t)(tok0 + tg * 2 + i) * NHEADS + hx] =
            make_float4(e0 * inv, e1 * inv, e2 * inv, 0.f);
    }
}

// ---------------------------------------------------------------------------
// Kernel 2: kv[tok][head][32] = hidden[tok, head*64:+64] @ Wd + bd  (f32x2)
// Grid: (64 token-tiles x 16 heads), 128 threads, thread = token.
// ---------------------------------------------------------------------------
__global__ __launch_bounds__(128) void k_kv(
    const float* __restrict__ hidden,
    const float* __restrict__ Wd,
    const float* __restrict__ bd)
{
    __shared__ u64 sWd2[64 * 16];   // [d][sd-pair]

    const int head = blockIdx.x & 15;
    const int tile = blockIdx.x >> 4;
    const int tid  = threadIdx.x;

    const u64* Wd2 = (const u64*)Wd;
#pragma unroll
    for (int i = tid; i < 1024; i += 128) sWd2[i] = Wd2[i];
    __syncthreads();

    const int token = tile * 128 + tid;
    const float4* hp = (const float4*)hidden + (size_t)token * 256 + head * 16;

    u64 acc[16];
    const u64* bd2 = (const u64*)bd;
#pragma unroll
    for (int j = 0; j < 16; j++) acc[j] = __ldg(&bd2[j]);

#pragma unroll
    for (int dc = 0; dc < 4; dc++) {
        float4 h4[4];
#pragma unroll
        for (int t = 0; t < 4; t++) h4[t] = __ldcs(&hp[dc * 4 + t]);
#pragma unroll
        for (int t = 0; t < 4; t++) {
            const int d0 = dc * 16 + t * 4;
            const float hv[4] = { h4[t].x, h4[t].y, h4[t].z, h4[t].w };
#pragma unroll
            for (int e = 0; e < 4; e++) {
                u64 hd = pack2(hv[e], hv[e]);
                const u64* wrow = &sWd2[(d0 + e) * 16];
#pragma unroll
                for (int j = 0; j < 16; j++) fma2(acc[j], hd, wrow[j]);
            }
        }
    }

    float4* kvout = g_kv4 + ((size_t)token * NHEADS + head) * 8;
#pragma unroll
    for (int j2 = 0; j2 < 8; j2++) {
        float2 lo = unpack2(acc[2 * j2]);
        float2 hi = unpack2(acc[2 * j2 + 1]);
        kvout[j2] = make_float4(lo.x, lo.y, hi.x, hi.y);
    }
}

// ---------------------------------------------------------------------------
// Kernel 3: stack update + gate softmax + mem. Warp = (token, head).
// No smem, no weights. Lane layout: g = lane>>3, c = lane&7; slot = i*4+g.
// ---------------------------------------------------------------------------
__global__ __launch_bounds__(256, 2) void k_stack(
    const float* __restrict__ stack,
    const float* __restrict__ mask,
    const float* __restrict__ Wg,
    const float* __restrict__ bg,
    float* __restrict__ new_stack,
    float* __restrict__ new_mask)
{
    const int tid  = threadIdx.x;
    const int wl   = tid >> 5;
    const int lane = tid & 31;
    const int g    = lane >> 3;
    const int c    = lane & 7;

    const size_t th = (size_t)blockIdx.x * 8 + wl;
    const float4* stk4 = (const float4*)stack + th * 128;

    float4 st[4];
#pragma unroll
    for (int i = 0; i < 4; i++) st[i] = __ldcs(&stk4[i * 32 + lane]);

    const float* mk = mask + th * SLOTS;
    float m[4], mn[4], mp[4];
#pragma unroll
    for (int i = 0; i < 4; i++) {
        const int slot = i * 4 + g;
        m[i]  = __ldcs(&mk[slot]);
        mn[i] = (slot < 15) ? __ldcs(&mk[slot + 1]) : 0.f;
        mp[i] = (slot > 0)  ? __ldcs(&mk[slot - 1]) : 1.f;
    }

    const float4 kv4 = __ldg(&g_kv4[th * 8 + c]);
    const float4 act = __ldg(&g_act4[th]);
    const float a_push = act.x, a_pop = act.y, a_noop = act.z;
    const float4 wg4 = __ldg(&((const float4*)Wg)[c]);

    // q[s] = Wg . stack[s]  (reduce over c)
    float q[4];
#pragma unroll
    for (int i = 0; i < 4; i++) {
        q[i] = dot4(st[i], wg4);
        q[i] += __shfl_xor_sync(FULLMASK, q[i], 1);
        q[i] += __shfl_xor_sync(FULLMASK, q[i], 2);
        q[i] += __shfl_xor_sync(FULLMASK, q[i], 4);
    }
    float qk = dot4(kv4, wg4);
    qk += __shfl_xor_sync(FULLMASK, qk, 1);
    qk += __shfl_xor_sync(FULLMASK, qk, 2);
    qk += __shfl_xor_sync(FULLMASK, qk, 4);

    // neighbors via send-rotation
    float qn[4], qp[4];
#pragma unroll
    for (int i = 0; i < 4; i++) {
        float sn = (g == 0) ? ((i < 3) ? q[i + 1] : 0.f) : q[i];
        qn[i] = __shfl_sync(FULLMASK, sn, (lane + 8) & 31);
        float sp = (g == 3) ? ((i > 0) ? q[i - 1] : 0.f) : q[i];
        qp[i] = __shfl_sync(FULLMASK, sp, (lane + 24) & 31);
    }
    if (g == 0) qp[0] = qk;

    // new_mask + gate scores + softmax
    const float bgv = __ldg(&bg[0]);
    float nm[4], e[4];
    float mx = -3.4e38f;
#pragma unroll
    for (int i = 0; i < 4; i++) {
        nm[i] = fmaf(a_push, mp[i], fmaf(a_pop, mn[i], a_noop * m[i]));
        float sc = fmaf(a_push, qp[i], fmaf(a_pop, qn[i], a_noop * q[i])) + bgv;
        sc += (1.f - nm[i]) * (-1e9f);
        e[i] = sc;
        mx = fmaxf(mx, sc);
    }
    mx = fmaxf(mx, __shfl_xor_sync(FULLMASK, mx, 8));
    mx = fmaxf(mx, __shfl_xor_sync(FULLMASK, mx, 16));
    float ssum = 0.f;
#pragma unroll
    for (int i = 0; i < 4; i++) { e[i] = __expf(e[i] - mx); ssum += e[i]; }
    ssum += __shfl_xor_sync(FULLMASK, ssum, 8);
    ssum += __shfl_xor_sync(FULLMASK, ssum, 16);
    const float ginv = 1.f / ssum;

    if (c == 0) {
#pragma unroll
        for (int i = 0; i < 4; i++)
            __stcs(&new_mask[th * SLOTS + i * 4 + g], nm[i]);
    }

    // neighbor stack values (L1 hits on just-loaded lines)
    float4 nx[4], pv[4];
#pragma unroll
    for (int i = 0; i < 4; i++) {
        const int slot = i * 4 + g;
        nx[i] = (slot < 15) ? __ldcs(&stk4[i * 32 + lane + 8]) : f4zero();
        pv[i] = (slot > 0)  ? __ldcs(&stk4[i * 32 + lane - 8]) : f4zero();
    }
    if (g == 0) pv[0] = kv4;

    float4* nst4 = (float4*)new_stack + th * 128;
    float4 acc = f4zero();
#pragma unroll
    for (int i = 0; i < 4; i++) {
        float4 ns;
        ns.x = fmaf(a_push, pv[i].x, fmaf(a_pop, nx[i].x, a_noop * st[i].x));
        ns.y = fmaf(a_push, pv[i].y, fmaf(a_pop, nx[i].y, a_noop * st[i].y));
        ns.z = fmaf(a_push, pv[i].z, fmaf(a_pop, nx[i].z, a_noop * st[i].z));
        ns.w = fmaf(a_push, pv[i].w, fmaf(a_pop, nx[i].w, a_noop * st[i].w));
        __stcs(&nst4[i * 32 + lane], ns);
        acc = f4fma(e[i] * ginv, ns, acc);
    }
    acc = f4add(acc, f4shflxor(acc, 8));
    acc = f4add(acc, f4shflxor(acc, 16));
    if (g == 0)
        g_mem4[th * 8 + c] = acc;
}

// ---------------------------------------------------------------------------
// Kernel 4: out = (mem @ Wu + bu) * rw + hidden  (f32x2)
// Grid: (64 token-tiles x 16 heads), 256 threads: token = tid&127, dhalf = tid>>7.
// ---------------------------------------------------------------------------
__global__ __launch_bounds__(256) void k_out(
    const float* __restrict__ hidden,
    const float* __restrict__ Wu,
    const float* __restrict__ bu,
    const float* __restrict__ res_w,
    float* __restrict__ out)
{
    __shared__ u64 sWu2[32 * 32];   // [sd][d-pair]

    const int head = blockIdx.x & 15;
    const int tile = blockIdx.x >> 4;
    const int tid  = threadIdx.x;
    const int token = tile * 128 + (tid & 127);
    const int dh    = tid >> 7;     // 0 or 1: d range [dh*32, dh*32+32)

    const u64* Wu2 = (const u64*)Wu;
#pragma unroll
    for (int i = tid; i < 1024; i += 256) sWu2[i] = Wu2[i];
    __syncthreads();

    const float4* mp = g_mem4 + ((size_t)token * NHEADS + head) * 8;
    float mreg[32];
#pragma unroll
    for (int j2 = 0; j2 < 8; j2++) {
        float4 v = mp[j2];
        mreg[4 * j2 + 0] = v.x; mreg[4 * j2 + 1] = v.y;
        mreg[4 * j2 + 2] = v.z; mreg[4 * j2 + 3] = v.w;
    }

    u64 acc[16];
    const u64* bu2 = (const u64*)bu;
#pragma unroll
    for (int j = 0; j < 16; j++) acc[j] = __ldg(&bu2[dh * 16 + j]);

#pragma unroll
    for (int sd = 0; sd < 32; sd++) {
        u64 md = pack2(mreg[sd], mreg[sd]);
        const u64* wrow = &sWu2[sd * 32 + dh * 16];
#pragma unroll
        for (int j = 0; j < 16; j++) fma2(acc[j], md, wrow[j]);
    }

    const float rw = __ldg(&res_w[0]);
    const size_t base = (size_t)token * 256 + head * 16 + dh * 8;
    const float4* hid4 = (const float4*)hidden + base;
    float4* out4 = (float4*)out + base;
#pragma unroll
    for (int j2 = 0; j2 < 8; j2++) {
        float2 lo = unpack2(acc[2 * j2]);
        float2 hi = unpack2(acc[2 * j2 + 1]);
        float4 h = __ldcs(&hid4[j2]);
        float4 o;
        o.x = fmaf(lo.x, rw, h.x);
        o.y = fmaf(lo.y, rw, h.y);
        o.z = fmaf(hi.x, rw, h.z);
        o.w = fmaf(hi.y, rw, h.w);
        __stcs(&out4[j2], o);
    }
}

// ---------------------------------------------------------------------------
extern "C" void kernel_launch(void* const* d_in, const int* in_sizes, int n_in,
                              void* d_out, int out_size)
{
    const float* hidden = (const float*)d_in[0];
    const float* stack  = (const float*)d_in[1];
    const float* mask   = (const float*)d_in[2];
    const float* Wa     = (const float*)d_in[3];
    const float* ba     = (const float*)d_in[4];
    const float* Wd     = (const float*)d_in[5];
    const float* bd     = (const float*)d_in[6];
    const float* Wu     = (const float*)d_in[7];
    const float* bu     = (const float*)d_in[8];
    const float* Wg     = (const float*)d_in[9];
    const float* bg     = (const float*)d_in[10];
    const float* res_w  = (const float*)d_in[11];

    float* out       = (float*)d_out;
    float* new_stack = out + (size_t)N_TOKENS * HDIM;
    float* new_mask  = new_stack + (size_t)N_TOKENS * NHEADS * SLOTS * SD;

    (void)in_sizes; (void)n_in; (void)out_size;

    k_waT<<<192, 256>>>(Wa);
    k_actions<<<N_TOKENS / 32, 256>>>(hidden, ba);
    k_kv<<<(N_TOKENS / 128) * NHEADS, 128>>>(hidden, Wd, bd);
    k_stack<<<N_TOKENS * NHEADS / 8, 256>>>(stack, mask, Wg, bg,
                                            new_stack, new_mask);
    k_out<<<(N_TOKENS / 128) * NHEADS, 256>>>(hidden, Wu, bu, res_w, out);
}

// round 5
// speedup vs baseline: 1.1376x; 1.1376x over previous
#include <cuda_runtime.h>
#include <cstdint>
#include <cstddef>

#define N_TOKENS 8192
#define HDIM     1024
#define NHEADS   16
#define SLOTS    16
#define SD       32
#define HD       64
#define FULLMASK 0xffffffffu

typedef unsigned long long u64;

__device__ float4 g_act4[N_TOKENS * NHEADS];
__device__ float  g_WaT[48 * HDIM];                      // WaT[col][k]
__device__ float  g_part[4 * N_TOKENS * 48];             // k-split partials
__device__ float4 g_kv4[(size_t)N_TOKENS * NHEADS * 8];  // kv [tok][head][32]
__device__ float4 g_mem4[(size_t)N_TOKENS * NHEADS * 8]; // mem [tok][head][32]

// ---------------------- helpers ----------------------
__device__ __forceinline__ u64 pack2(float x, float y) {
    u64 r; asm("mov.b64 %0,{%1,%2};" : "=l"(r) : "f"(x), "f"(y)); return r;
}
__device__ __forceinline__ void fma2(u64& d, u64 a, u64 b) {
    asm("fma.rn.f32x2 %0,%1,%2,%0;" : "+l"(d) : "l"(a), "l"(b));
}
__device__ __forceinline__ float2 unpack2(u64 v) {
    float2 r; asm("mov.b64 {%0,%1},%2;" : "=f"(r.x), "=f"(r.y) : "l"(v)); return r;
}
__device__ __forceinline__ float4 f4zero() { return make_float4(0.f, 0.f, 0.f, 0.f); }
__device__ __forceinline__ float4 f4fma(float a, float4 b, float4 c) {
    return make_float4(fmaf(a, b.x, c.x), fmaf(a, b.y, c.y),
                       fmaf(a, b.z, c.z), fmaf(a, b.w, c.w));
}
__device__ __forceinline__ float4 f4add(float4 a, float4 b) {
    return make_float4(a.x + b.x, a.y + b.y, a.z + b.z, a.w + b.w);
}
__device__ __forceinline__ float dot4(float4 a, float4 b) {
    return fmaf(a.x, b.x, fmaf(a.y, b.y, fmaf(a.z, b.z, a.w * b.w)));
}
__device__ __forceinline__ float4 f4shflxor(float4 v, int m) {
    return make_float4(__shfl_xor_sync(FULLMASK, v.x, m),
                       __shfl_xor_sync(FULLMASK, v.y, m),
                       __shfl_xor_sync(FULLMASK, v.z, m),
                       __shfl_xor_sync(FULLMASK, v.w, m));
}

// ---------------------------------------------------------------------------
// Kernel 0: transpose Wa [1024][48] -> g_WaT [48][1024]
// ---------------------------------------------------------------------------
__global__ __launch_bounds__(256) void k_waT(const float* __restrict__ Wa)
{
    const int col = blockIdx.x >> 2;
    const int k   = (blockIdx.x & 3) * 256 + threadIdx.x;
    g_WaT[col * HDIM + k] = Wa[(size_t)k * 48 + col];
}

// ---------------------------------------------------------------------------
// Kernel 1a: partial logits GEMM. Block = 128 tok x 48 col x 256-k chunk.
// Thread tile: 4 tok x 6 col. grid = 64 tiles x 4 k-chunks.
// ---------------------------------------------------------------------------
__global__ __launch_bounds__(256) void k_actions_part(
    const float* __restrict__ hidden)
{
    __shared__ __align__(16) float sA[128][68];
    __shared__ __align__(16) float sWT[48][68];

    const int tid  = threadIdx.x;
    const int ty   = tid >> 3;       // 0..31 -> 4 tokens each
    const int tx   = tid & 7;        // 0..7  -> 6 cols each
    const int tile = blockIdx.x >> 2;
    const int kc   = blockIdx.x & 3;
    const int tok0 = tile * 128;
    const float4* hid4 = (const float4*)hidden;
    const float4* waT4 = (const float4*)g_WaT;

    u64 acc[4][6];
#pragma unroll
    for (int t = 0; t < 4; t++)
#pragma unroll
        for (int j = 0; j < 6; j++) acc[t][j] = 0ull;

#pragma unroll
    for (int sub = 0; sub < 4; sub++) {
        const int k4 = kc * 64 + sub * 16;   // f4 base index in k
#pragma unroll
        for (int idx = tid; idx < 2048; idx += 256) {
            int r = idx >> 4, c4 = idx & 15;
            *(float4*)&sA[r][c4 * 4] = hid4[(size_t)(tok0 + r) * 256 + k4 + c4];
        }
#pragma unroll
        for (int idx = tid; idx < 768; idx += 256) {
            int r = idx >> 4, c4 = idx & 15;
            *(float4*)&sWT[r][c4 * 4] = waT4[(size_t)r * 256 + k4 + c4];
        }
        __syncthreads();

#pragma unroll 8
        for (int k2 = 0; k2 < 32; k2++) {
            u64 a[4];
#pragma unroll
            for (int t = 0; t < 4; t++)
                a[t] = *(const u64*)&sA[ty * 4 + t][k2 * 2];
#pragma unroll
            for (int j = 0; j < 6; j++) {
                u64 w = *(const u64*)&sWT[tx * 6 + j][k2 * 2];
                fma2(acc[0][j], a[0], w);
                fma2(acc[1][j], a[1], w);
                fma2(acc[2][j], a[2], w);
                fma2(acc[3][j], a[3], w);
            }
        }
        __syncthreads();
    }

#pragma unroll
    for (int t = 0; t < 4; t++) {
        const size_t base = ((size_t)kc * N_TOKENS + tok0 + ty * 4 + t) * 48 + tx * 6;
#pragma unroll
        for (int j2 = 0; j2 < 3; j2++) {
            float2 pa = unpack2(acc[t][j2 * 2]);
            float2 pb = unpack2(acc[t][j2 * 2 + 1]);
            *(float2*)&g_part[base + j2 * 2] = make_float2(pa.x + pa.y, pb.x + pb.y);
        }
    }
}

// ---------------------------------------------------------------------------
// Kernel 1b: reduce partials + softmax_3 -> g_act4. Thread = (token, head).
// ---------------------------------------------------------------------------
__global__ __launch_bounds__(256) void k_act_reduce(const float* __restrict__ ba)
{
    const int tid   = threadIdx.x;
    const int head  = tid & 15;
    const int token = blockIdx.x * 16 + (tid >> 4);

    float l[3];
#pragma unroll
    for (int j = 0; j < 3; j++) {
        const size_t col = (size_t)token * 48 + head * 3 + j;
        float s = g_part[col]
                + g_part[(size_t)N_TOKENS * 48 + col]
                + g_part[(size_t)2 * N_TOKENS * 48 + col]
                + g_part[(size_t)3 * N_TOKENS * 48 + col];
        l[j] = (s + __ldg(&ba[head * 3 + j])) * 0.125f;
    }
    float mx = fmaxf(l[0], fmaxf(l[1], l[2]));
    float e0 = __expf(l[0] - mx);
    float e1 = __expf(l[1] - mx);
    float e2 = __expf(l[2] - mx);
    float inv = 1.f / (e0 + e1 + e2);
    g_act4[(size_t)token * NHEADS + head] = make_float4(e0 * inv, e1 * inv, e2 * inv, 0.f);
}

// ---------------------------------------------------------------------------
// Kernel 2: kv = hidden-slice @ Wd + bd. Block = 8 tokens x 16 heads,
// 128 threads: h=tid>>3, jg=(tid>>1)&3 (4 sd-pairs), tg=tid&1 (4 tokens).
// ---------------------------------------------------------------------------
__global__ __launch_bounds__(128) void k_kv(
    const float* __restrict__ hidden,
    const float* __restrict__ Wd,
    const float* __restrict__ bd)
{
    __shared__ float sH2[NHEADS * 516];   // [h][d(64)*8tok + pad4]
    __shared__ u64   sWd2[64 * 16];       // [d][sd-pair]

    const int tid = threadIdx.x;
    const int h   = tid >> 3;
    const int jg  = (tid >> 1) & 3;
    const int tg  = tid & 1;
    const int tok0 = blockIdx.x * 8;
    const float4* hid4 = (const float4*)hidden;

    // fill weights
    const u64* Wd2 = (const u64*)Wd;
#pragma unroll
    for (int i = tid; i < 1024; i += 128) sWd2[i] = Wd2[i];
    // fill hidden transposed: sH2[h][d*8 + tok]
#pragma unroll
    for (int idx = tid; idx < 2048; idx += 128) {
        int tok = idx >> 8, c4 = idx & 255;
        float4 v = __ldcs(&hid4[(size_t)(tok0 + tok) * 256 + c4]);
        int d = c4 * 4;
        sH2[(d >> 6) * 516 + (d & 63) * 8 + tok]       = v.x;
        sH2[((d+1) >> 6) * 516 + ((d+1) & 63) * 8 + tok] = v.y;
        sH2[((d+2) >> 6) * 516 + ((d+2) & 63) * 8 + tok] = v.z;
        sH2[((d+3) >> 6) * 516 + ((d+3) & 63) * 8 + tok] = v.w;
    }
    __syncthreads();

    u64 acc[4][4];
    const u64* bd2 = (const u64*)bd;
#pragma unroll
    for (int j = 0; j < 4; j++) {
        u64 b = __ldg(&bd2[jg * 4 + j]);
        acc[0][j] = b; acc[1][j] = b; acc[2][j] = b; acc[3][j] = b;
    }

    const float* hbase = &sH2[h * 516 + tg * 4];
#pragma unroll 8
    for (int d = 0; d < HD; d++) {
        float4 h4 = *(const float4*)&hbase[d * 8];  // 4 tokens
        u64 hd[4];
        hd[0] = pack2(h4.x, h4.x); hd[1] = pack2(h4.y, h4.y);
        hd[2] = pack2(h4.z, h4.z); hd[3] = pack2(h4.w, h4.w);
#pragma unroll
        for (int j = 0; j < 4; j++) {
            u64 w = sWd2[d * 16 + jg * 4 + j];
            fma2(acc[0][j], hd[0], w);
            fma2(acc[1][j], hd[1], w);
            fma2(acc[2][j], hd[2], w);
            fma2(acc[3][j], hd[3], w);
        }
    }

#pragma unroll
    for (int t = 0; t < 4; t++) {
        const int token = tok0 + tg * 4 + t;
        float4* kvout = g_kv4 + ((size_t)token * NHEADS + h) * 8 + jg * 2;
        float2 aa = unpack2(acc[t][0]);
        float2 ab = unpack2(acc[t][1]);
        float2 ac = unpack2(acc[t][2]);
        float2 ad = unpack2(acc[t][3]);
        kvout[0] = make_float4(aa.x, aa.y, ab.x, ab.y);
        kvout[1] = make_float4(ac.x, ac.y, ad.x, ad.y);
    }
}

// ---------------------------------------------------------------------------
// Kernel 3: stack update + gate softmax + mem. Warp = (token, head).
// Lane layout: g = lane>>3, c = lane&7; slot = i*4+g.
// ---------------------------------------------------------------------------
__global__ __launch_bounds__(256, 3) void k_stack(
    const float* __restrict__ stack,
    const float* __restrict__ mask,
    const float* __restrict__ Wg,
    const float* __restrict__ bg,
    float* __restrict__ new_stack,
    float* __restrict__ new_mask)
{
    const int tid  = threadIdx.x;
    const int wl   = tid >> 5;
    const int lane = tid & 31;
    const int g    = lane >> 3;
    const int c    = lane & 7;

    const size_t th = (size_t)blockIdx.x * 8 + wl;
    const float4* stk4 = (const float4*)stack + th * 128;

    float4 st[4];
#pragma unroll
    for (int i = 0; i < 4; i++) st[i] = __ldcs(&stk4[i * 32 + lane]);

    const float4 kv4 = __ldg(&g_kv4[th * 8 + c]);
    const float4 act = __ldg(&g_act4[th]);
    const float a_push = act.x, a_pop = act.y, a_noop = act.z;
    const float4 wg4 = __ldg(&((const float4*)Wg)[c]);

    // q[s] = Wg . stack[s]  (reduce over c)
    float q[4];
#pragma unroll
    for (int i = 0; i < 4; i++) {
        q[i] = dot4(st[i], wg4);
        q[i] += __shfl_xor_sync(FULLMASK, q[i], 1);
        q[i] += __shfl_xor_sync(FULLMASK, q[i], 2);
        q[i] += __shfl_xor_sync(FULLMASK, q[i], 4);
    }
    float qk = dot4(kv4, wg4);
    qk += __shfl_xor_sync(FULLMASK, qk, 1);
    qk += __shfl_xor_sync(FULLMASK, qk, 2);
    qk += __shfl_xor_sync(FULLMASK, qk, 4);

    // neighbor q via send-rotation
    float qn[4], qp[4];
#pragma unroll
    for (int i = 0; i < 4; i++) {
        float sn = (g == 0) ? ((i < 3) ? q[i + 1] : 0.f) : q[i];
        qn[i] = __shfl_sync(FULLMASK, sn, (lane + 8) & 31);
        float sp = (g == 3) ? ((i > 0) ? q[i - 1] : 0.f) : q[i];
        qp[i] = __shfl_sync(FULLMASK, sp, (lane + 24) & 31);
    }
    if (g == 0) qp[0] = qk;

    // masks + gate scores (mask loads inline to cut live registers)
    const float bgv = __ldg(&bg[0]);
    const float* mk = mask + th * SLOTS;
    float nm[4], e[4];
    float mx = -3.4e38f;
#pragma unroll
    for (int i = 0; i < 4; i++) {
        const int slot = i * 4 + g;
        float m  = __ldcs(&mk[slot]);
        float mn = (slot < 15) ? __ldcs(&mk[slot + 1]) : 0.f;
        float mp = (slot > 0)  ? __ldcs(&mk[slot - 1]) : 1.f;
        nm[i] = fmaf(a_push, mp, fmaf(a_pop, mn, a_noop * m));
        float sc = fmaf(a_push, qp[i], fmaf(a_pop, qn[i], a_noop * q[i])) + bgv;
        sc += (1.f - nm[i]) * (-1e9f);
        e[i] = sc;
        mx = fmaxf(mx, sc);
    }
    mx = fmaxf(mx, __shfl_xor_sync(FULLMASK, mx, 8));
    mx = fmaxf(mx, __shfl_xor_sync(FULLMASK, mx, 16));
    float ssum = 0.f;
#pragma unroll
    for (int i = 0; i < 4; i++) { e[i] = __expf(e[i] - mx); ssum += e[i]; }
    ssum += __shfl_xor_sync(FULLMASK, ssum, 8);
    ssum += __shfl_xor_sync(FULLMASK, ssum, 16);
    const float ginv = 1.f / ssum;

    if (c == 0) {
#pragma unroll
        for (int i = 0; i < 4; i++)
            __stcs(&new_mask[th * SLOTS + i * 4 + g], nm[i]);
    }

    // stack update: neighbors re-read inline (L1 hits), store + accumulate
    float4* nst4 = (float4*)new_stack + th * 128;
    float4 acc = f4zero();
#pragma unroll
    for (int i = 0; i < 4; i++) {
        const int slot = i * 4 + g;
        float4 nx = (slot < 15) ? __ldcs(&stk4[i * 32 + lane + 8]) : f4zero();
        float4 pv = (slot > 0)  ? __ldcs(&stk4[i * 32 + lane - 8]) : kv4;
        float4 ns;
        ns.x = fmaf(a_push, pv.x, fmaf(a_pop, nx.x, a_noop * st[i].x));
        ns.y = fmaf(a_push, pv.y, fmaf(a_pop, nx.y, a_noop * st[i].y));
        ns.z = fmaf(a_push, pv.z, fmaf(a_pop, nx.z, a_noop * st[i].z));
        ns.w = fmaf(a_push, pv.w, fmaf(a_pop, nx.w, a_noop * st[i].w));
        __stcs(&nst4[i * 32 + lane], ns);
        acc = f4fma(e[i] * ginv, ns, acc);
    }
    acc = f4add(acc, f4shflxor(acc, 8));
    acc = f4add(acc, f4shflxor(acc, 16));
    if (g == 0)
        g_mem4[th * 8 + c] = acc;
}

// ---------------------------------------------------------------------------
// Kernel 4: out = (mem @ Wu + bu)*rw + hidden. Block = 8 tok x 16 heads,
// 256 threads: h=tid>>4, dg=(tid>>1)&7 (4 d-pairs), tg=tid&1 (4 tokens).
// ---------------------------------------------------------------------------
__global__ __launch_bounds__(256) void k_out(
    const float* __restrict__ hidden,
    const float* __restrict__ Wu,
    const float* __restrict__ bu,
    const float* __restrict__ res_w,
    float* __restrict__ out)
{
    __shared__ float sM2[NHEADS * 260];   // [h][sd(32)*8tok + pad4]
    __shared__ u64   sWu2[32 * 32];       // [sd][d-pair]

    const int tid = threadIdx.x;
    const int h   = tid >> 4;
    const int dg  = (tid >> 1) & 7;
    const int tg  = tid & 1;
    const int tok0 = blockIdx.x * 8;

    const u64* Wu2 = (const u64*)Wu;
#pragma unroll
    for (int i = tid; i < 1024; i += 256) sWu2[i] = Wu2[i];
#pragma unroll
    for (int idx = tid; idx < 1024; idx += 256) {
        int tok = idx >> 7, r = idx & 127;      // r = h*8 + j2
        int hh = r >> 3, j2 = r & 7;
        float4 v = g_mem4[((size_t)(tok0 + tok) * NHEADS + hh) * 8 + j2];
        int sd = j2 * 4;
        sM2[hh * 260 + (sd + 0) * 8 + tok] = v.x;
        sM2[hh * 260 + (sd + 1) * 8 + tok] = v.y;
        sM2[hh * 260 + (sd + 2) * 8 + tok] = v.z;
        sM2[hh * 260 + (sd + 3) * 8 + tok] = v.w;
    }
    __syncthreads();

    u64 acc[4][4];
    const u64* bu2 = (const u64*)bu;
#pragma unroll
    for (int j = 0; j < 4; j++) {
        u64 b = __ldg(&bu2[dg * 4 + j]);
        acc[0][j] = b; acc[1][j] = b; acc[2][j] = b; acc[3][j] = b;
    }

    const float* mbase = &sM2[h * 260 + tg * 4];
#pragma unroll 8
    for (int sd = 0; sd < SD; sd++) {
        float4 m4 = *(const float4*)&mbase[sd * 8];   // 4 tokens
        u64 md[4];
        md[0] = pack2(m4.x, m4.x); md[1] = pack2(m4.y, m4.y);
        md[2] = pack2(m4.z, m4.z); md[3] = pack2(m4.w, m4.w);
#pragma unroll
        for (int j = 0; j < 4; j++) {
            u64 w = sWu2[sd * 32 + dg * 4 + j];
            fma2(acc[0][j], md[0], w);
            fma2(acc[1][j], md[1], w);
            fma2(acc[2][j], md[2], w);
            fma2(acc[3][j], md[3], w);
        }
    }

    const float rw = __ldg(&res_w[0]);
#pragma unroll
    for (int t = 0; t < 4; t++) {
        const int token = tok0 + tg * 4 + t;
        const size_t base = (size_t)token * 256 + h * 16 + dg * 2;  // float4 units
        const float4* hid4 = (const float4*)hidden + base;
        float4* out4 = (float4*)out + base;
        float2 aa = unpack2(acc[t][0]);
        float2 ab = unpack2(acc[t][1]);
        float2 ac = unpack2(acc[t][2]);
        float2 ad = unpack2(acc[t][3]);
        float4 h0 = __ldcs(&hid4[0]);
        float4 h1 = __ldcs(&hid4[1]);
        float4 o0, o1;
        o0.x = fmaf(aa.x, rw, h0.x); o0.y = fmaf(aa.y, rw, h0.y);
        o0.z = fmaf(ab.x, rw, h0.z); o0.w = fmaf(ab.y, rw, h0.w);
        o1.x = fmaf(ac.x, rw, h1.x); o1.y = fmaf(ac.y, rw, h1.y);
        o1.z = fmaf(ad.x, rw, h1.z); o1.w = fmaf(ad.y, rw, h1.w);
        __stcs(&out4[0], o0);
        __stcs(&out4[1], o1);
    }
}

// ---------------------------------------------------------------------------
extern "C" void kernel_launch(void* const* d_in, const int* in_sizes, int n_in,
                              void* d_out, int out_size)
{
    const float* hidden = (const float*)d_in[0];
    const float* stack  = (const float*)d_in[1];
    const float* mask   = (const float*)d_in[2];
    const float* Wa     = (const float*)d_in[3];
    const float* ba     = (const float*)d_in[4];
    const float* Wd     = (const float*)d_in[5];
    const float* bd     = (const float*)d_in[6];
    const float* Wu     = (const float*)d_in[7];
    const float* bu     = (const float*)d_in[8];
    const float* Wg     = (const float*)d_in[9];
    const float* bg     = (const float*)d_in[10];
    const float* res_w  = (const float*)d_in[11];

    float* out       = (float*)d_out;
    float* new_stack = out + (size_t)N_TOKENS * HDIM;
    float* new_mask  = new_stack + (size_t)N_TOKENS * NHEADS * SLOTS * SD;

    (void)in_sizes; (void)n_in; (void)out_size;

    k_waT<<<192, 256>>>(Wa);
    k_actions_part<<<256, 256>>>(hidden);
    k_act_reduce<<<N_TOKENS / 16, 256>>>(ba);
    k_kv<<<N_TOKENS / 8, 128>>>(hidden, Wd, bd);
    k_stack<<<N_TOKENS * NHEADS / 8, 256>>>(stack, mask, Wg, bg,
                                            new_stack, new_mask);
    k_out<<<N_TOKENS / 8, 256>>>(hidden, Wu, bu, res_w, out);
}

// round 6
// speedup vs baseline: 1.1634x; 1.0226x over previous
#include <cuda_runtime.h>
#include <cstdint>
#include <cstddef>

#define N_TOKENS 8192
#define HDIM     1024
#define NHEADS   16
#define SLOTS    16
#define SD       32
#define HD       64
#define FULLMASK 0xffffffffu

typedef unsigned long long u64;

__device__ float4 g_act4[N_TOKENS * NHEADS];
__device__ float  g_WaT[48 * HDIM];                      // WaT[col][k]
__device__ float  g_part[4 * N_TOKENS * 48];             // k-split partials
__device__ float4 g_kv4[(size_t)N_TOKENS * NHEADS * 8];  // kv [tok][head][32]
__device__ float4 g_mem4[(size_t)N_TOKENS * NHEADS * 8]; // mem [tok][head][32]

// ---------------------- helpers ----------------------
__device__ __forceinline__ u64 pack2(float x, float y) {
    u64 r; asm("mov.b64 %0,{%1,%2};" : "=l"(r) : "f"(x), "f"(y)); return r;
}
__device__ __forceinline__ void fma2(u64& d, u64 a, u64 b) {
    asm("fma.rn.f32x2 %0,%1,%2,%0;" : "+l"(d) : "l"(a), "l"(b));
}
__device__ __forceinline__ float2 unpack2(u64 v) {
    float2 r; asm("mov.b64 {%0,%1},%2;" : "=f"(r.x), "=f"(r.y) : "l"(v)); return r;
}
__device__ __forceinline__ float4 f4zero() { return make_float4(0.f, 0.f, 0.f, 0.f); }
__device__ __forceinline__ float4 f4fma(float a, float4 b, float4 c) {
    return make_float4(fmaf(a, b.x, c.x), fmaf(a, b.y, c.y),
                       fmaf(a, b.z, c.z), fmaf(a, b.w, c.w));
}
__device__ __forceinline__ float4 f4add(float4 a, float4 b) {
    return make_float4(a.x + b.x, a.y + b.y, a.z + b.z, a.w + b.w);
}
__device__ __forceinline__ float dot4(float4 a, float4 b) {
    return fmaf(a.x, b.x, fmaf(a.y, b.y, fmaf(a.z, b.z, a.w * b.w)));
}
__device__ __forceinline__ float4 f4shflxor(float4 v, int m) {
    return make_float4(__shfl_xor_sync(FULLMASK, v.x, m),
                       __shfl_xor_sync(FULLMASK, v.y, m),
                       __shfl_xor_sync(FULLMASK, v.z, m),
                       __shfl_xor_sync(FULLMASK, v.w, m));
}

// ---------------------------------------------------------------------------
// Kernel 0: transpose Wa [1024][48] -> g_WaT [48][1024]
// ---------------------------------------------------------------------------
__global__ __launch_bounds__(256) void k_waT(const float* __restrict__ Wa)
{
    const int col = blockIdx.x >> 2;
    const int k   = (blockIdx.x & 3) * 256 + threadIdx.x;
    g_WaT[col * HDIM + k] = Wa[(size_t)k * 48 + col];
}

// ---------------------------------------------------------------------------
// Kernel 1a: partial logits GEMM. Block = 128 tok x 48 col x 256-k chunk.
// ---------------------------------------------------------------------------
__global__ __launch_bounds__(256) void k_actions_part(
    const float* __restrict__ hidden)
{
    __shared__ __align__(16) float sA[128][68];
    __shared__ __align__(16) float sWT[48][68];

    const int tid  = threadIdx.x;
    const int ty   = tid >> 3;
    const int tx   = tid & 7;
    const int tile = blockIdx.x >> 2;
    const int kc   = blockIdx.x & 3;
    const int tok0 = tile * 128;
    const float4* hid4 = (const float4*)hidden;
    const float4* waT4 = (const float4*)g_WaT;

    u64 acc[4][6];
#pragma unroll
    for (int t = 0; t < 4; t++)
#pragma unroll
        for (int j = 0; j < 6; j++) acc[t][j] = 0ull;

#pragma unroll
    for (int sub = 0; sub < 4; sub++) {
        const int k4 = kc * 64 + sub * 16;
#pragma unroll
        for (int idx = tid; idx < 2048; idx += 256) {
            int r = idx >> 4, c4 = idx & 15;
            *(float4*)&sA[r][c4 * 4] = hid4[(size_t)(tok0 + r) * 256 + k4 + c4];
        }
#pragma unroll
        for (int idx = tid; idx < 768; idx += 256) {
            int r = idx >> 4, c4 = idx & 15;
            *(float4*)&sWT[r][c4 * 4] = waT4[(size_t)r * 256 + k4 + c4];
        }
        __syncthreads();

#pragma unroll 8
        for (int k2 = 0; k2 < 32; k2++) {
            u64 a[4];
#pragma unroll
            for (int t = 0; t < 4; t++)
                a[t] = *(const u64*)&sA[ty * 4 + t][k2 * 2];
#pragma unroll
            for (int j = 0; j < 6; j++) {
                u64 w = *(const u64*)&sWT[tx * 6 + j][k2 * 2];
                fma2(acc[0][j], a[0], w);
                fma2(acc[1][j], a[1], w);
                fma2(acc[2][j], a[2], w);
                fma2(acc[3][j], a[3], w);
            }
        }
        __syncthreads();
    }

#pragma unroll
    for (int t = 0; t < 4; t++) {
        const size_t base = ((size_t)kc * N_TOKENS + tok0 + ty * 4 + t) * 48 + tx * 6;
#pragma unroll
        for (int j2 = 0; j2 < 3; j2++) {
            float2 pa = unpack2(acc[t][j2 * 2]);
            float2 pb = unpack2(acc[t][j2 * 2 + 1]);
            *(float2*)&g_part[base + j2 * 2] = make_float2(pa.x + pa.y, pb.x + pb.y);
        }
    }
}

// ---------------------------------------------------------------------------
// Kernel 1b: reduce partials + softmax_3 -> g_act4.
// ---------------------------------------------------------------------------
__global__ __launch_bounds__(256) void k_act_reduce(const float* __restrict__ ba)
{
    const int tid   = threadIdx.x;
    const int head  = tid & 15;
    const int token = blockIdx.x * 16 + (tid >> 4);

    float l[3];
#pragma unroll
    for (int j = 0; j < 3; j++) {
        const size_t col = (size_t)token * 48 + head * 3 + j;
        float s = g_part[col]
                + g_part[(size_t)N_TOKENS * 48 + col]
                + g_part[(size_t)2 * N_TOKENS * 48 + col]
                + g_part[(size_t)3 * N_TOKENS * 48 + col];
        l[j] = (s + __ldg(&ba[head * 3 + j])) * 0.125f;
    }
    float mx = fmaxf(l[0], fmaxf(l[1], l[2]));
    float e0 = __expf(l[0] - mx);
    float e1 = __expf(l[1] - mx);
    float e2 = __expf(l[2] - mx);
    float inv = 1.f / (e0 + e1 + e2);
    g_act4[(size_t)token * NHEADS + head] = make_float4(e0 * inv, e1 * inv, e2 * inv, 0.f);
}

// ---------------------------------------------------------------------------
// Kernel 2: kv = hidden-slice @ Wd + bd. Block = 128 tok x 1 head, 256 thr.
// tg = tid>>3 (4 tokens), jg = tid&7 (sd f4 group = pairs 2jg,2jg+1).
// A tile transposed [d][tok], XOR swizzle (f4col = tg ^ (d&31)).
// ---------------------------------------------------------------------------
__global__ __launch_bounds__(256) void k_kv(
    const float* __restrict__ hidden,
    const float* __restrict__ Wd,
    const float* __restrict__ bd)
{
    __shared__ __align__(16) float sAT[64 * 128];   // 32 KB
    __shared__ __align__(16) u64   sWd2[64 * 16];   // 8 KB [d][pair]

    const int tid  = threadIdx.x;
    const int head = blockIdx.x & 15;
    const int tok0 = (blockIdx.x >> 4) * 128;
    const int jg   = tid & 7;
    const int tg   = tid >> 3;

    // weights fill (contiguous)
    ((float4*)sWd2)[tid]       = ((const float4*)Wd)[tid];
    ((float4*)sWd2)[tid + 256] = ((const float4*)Wd)[tid + 256];

    // A fill: coalesced gmem read, swizzled scalar smem write
    const float4* hid4 = (const float4*)hidden;
#pragma unroll
    for (int k = 0; k < 8; k++) {
        int idx = k * 256 + tid;
        int tok = idx >> 4, c4 = idx & 15;
        float4 v = __ldcs(&hid4[(size_t)(tok0 + tok) * 256 + head * 16 + c4]);
        int d0 = c4 * 4;
        const int tq = tok >> 2, tr = tok & 3;
        sAT[(d0 + 0) * 128 + ((tq ^ ((d0 + 0) & 31)) << 2) + tr] = v.x;
        sAT[(d0 + 1) * 128 + ((tq ^ ((d0 + 1) & 31)) << 2) + tr] = v.y;
        sAT[(d0 + 2) * 128 + ((tq ^ ((d0 + 2) & 31)) << 2) + tr] = v.z;
        sAT[(d0 + 3) * 128 + ((tq ^ ((d0 + 3) & 31)) << 2) + tr] = v.w;
    }
    __syncthreads();

    u64 acc[4][2];
    {
        const u64* bd2 = (const u64*)bd;
        u64 b0 = __ldg(&bd2[jg * 2]);
        u64 b1 = __ldg(&bd2[jg * 2 + 1]);
#pragma unroll
        for (int t = 0; t < 4; t++) { acc[t][0] = b0; acc[t][1] = b1; }
    }

#pragma unroll 16
    for (int d = 0; d < HD; d++) {
        float4 a4 = *(const float4*)&sAT[d * 128 + ((tg ^ (d & 31)) << 2)];
        const u64* wp = &sWd2[d * 16 + jg * 2];
        u64 w0 = wp[0], w1 = wp[1];
        u64 h0 = pack2(a4.x, a4.x), h1 = pack2(a4.y, a4.y);
        u64 h2 = pack2(a4.z, a4.z), h3 = pack2(a4.w, a4.w);
        fma2(acc[0][0], h0, w0); fma2(acc[0][1], h0, w1);
        fma2(acc[1][0], h1, w0); fma2(acc[1][1], h1, w1);
        fma2(acc[2][0], h2, w0); fma2(acc[2][1], h2, w1);
        fma2(acc[3][0], h3, w0); fma2(acc[3][1], h3, w1);
    }

    float4* kvout = g_kv4 + ((size_t)(tok0 + tg * 4) * NHEADS + head) * 8 + jg;
#pragma unroll
    for (int t = 0; t < 4; t++) {
        float2 lo = unpack2(acc[t][0]);
        float2 hi = unpack2(acc[t][1]);
        kvout[t * 128] = make_float4(lo.x, lo.y, hi.x, hi.y);
    }
}

// ---------------------------------------------------------------------------
// Kernel 3: stack update + gate softmax + mem. Warp = (token, head).
// ---------------------------------------------------------------------------
__global__ __launch_bounds__(256, 3) void k_stack(
    const float* __restrict__ stack,
    const float* __restrict__ mask,
    const float* __restrict__ Wg,
    const float* __restrict__ bg,
    float* __restrict__ new_stack,
    float* __restrict__ new_mask)
{
    const int tid  = threadIdx.x;
    const int wl   = tid >> 5;
    const int lane = tid & 31;
    const int g    = lane >> 3;
    const int c    = lane & 7;

    const size_t th = (size_t)blockIdx.x * 8 + wl;
    const float4* stk4 = (const float4*)stack + th * 128;

    float4 st[4];
#pragma unroll
    for (int i = 0; i < 4; i++) st[i] = __ldcs(&stk4[i * 32 + lane]);

    const float4 kv4 = __ldg(&g_kv4[th * 8 + c]);
    const float4 act = __ldg(&g_act4[th]);
    const float a_push = act.x, a_pop = act.y, a_noop = act.z;
    const float4 wg4 = __ldg(&((const float4*)Wg)[c]);

    float q[4];
#pragma unroll
    for (int i = 0; i < 4; i++) {
        q[i] = dot4(st[i], wg4);
        q[i] += __shfl_xor_sync(FULLMASK, q[i], 1);
        q[i] += __shfl_xor_sync(FULLMASK, q[i], 2);
        q[i] += __shfl_xor_sync(FULLMASK, q[i], 4);
    }
    float qk = dot4(kv4, wg4);
    qk += __shfl_xor_sync(FULLMASK, qk, 1);
    qk += __shfl_xor_sync(FULLMASK, qk, 2);
    qk += __shfl_xor_sync(FULLMASK, qk, 4);

    float qn[4], qp[4];
#pragma unroll
    for (int i = 0; i < 4; i++) {
        float sn = (g == 0) ? ((i < 3) ? q[i + 1] : 0.f) : q[i];
        qn[i] = __shfl_sync(FULLMASK, sn, (lane + 8) & 31);
        float sp = (g == 3) ? ((i > 0) ? q[i - 1] : 0.f) : q[i];
        qp[i] = __shfl_sync(FULLMASK, sp, (lane + 24) & 31);
    }
    if (g == 0) qp[0] = qk;

    const float bgv = __ldg(&bg[0]);
    const float* mk = mask + th * SLOTS;
    float nm[4], e[4];
    float mx = -3.4e38f;
#pragma unroll
    for (int i = 0; i < 4; i++) {
        const int slot = i * 4 + g;
        float m  = __ldcs(&mk[slot]);
        float mn = (slot < 15) ? __ldcs(&mk[slot + 1]) : 0.f;
        float mp = (slot > 0)  ? __ldcs(&mk[slot - 1]) : 1.f;
        nm[i] = fmaf(a_push, mp, fmaf(a_pop, mn, a_noop * m));
        float sc = fmaf(a_push, qp[i], fmaf(a_pop, qn[i], a_noop * q[i])) + bgv;
        sc += (1.f - nm[i]) * (-1e9f);
        e[i] = sc;
        mx = fmaxf(mx, sc);
    }
    mx = fmaxf(mx, __shfl_xor_sync(FULLMASK, mx, 8));
    mx = fmaxf(mx, __shfl_xor_sync(FULLMASK, mx, 16));
    float ssum = 0.f;
#pragma unroll
    for (int i = 0; i < 4; i++) { e[i] = __expf(e[i] - mx); ssum += e[i]; }
    ssum += __shfl_xor_sync(FULLMASK, ssum, 8);
    ssum += __shfl_xor_sync(FULLMASK, ssum, 16);
    const float ginv = 1.f / ssum;

    if (c == 0) {
#pragma unroll
        for (int i = 0; i < 4; i++)
            __stcs(&new_mask[th * SLOTS + i * 4 + g], nm[i]);
    }

    float4* nst4 = (float4*)new_stack + th * 128;
    float4 acc = f4zero();
#pragma unroll
    for (int i = 0; i < 4; i++) {
        const int slot = i * 4 + g;
        float4 nx = (slot < 15) ? __ldcs(&stk4[i * 32 + lane + 8]) : f4zero();
        float4 pv = (slot > 0)  ? __ldcs(&stk4[i * 32 + lane - 8]) : kv4;
        float4 ns;
        ns.x = fmaf(a_push, pv.x, fmaf(a_pop, nx.x, a_noop * st[i].x));
        ns.y = fmaf(a_push, pv.y, fmaf(a_pop, nx.y, a_noop * st[i].y));
        ns.z = fmaf(a_push, pv.z, fmaf(a_pop, nx.z, a_noop * st[i].z));
        ns.w = fmaf(a_push, pv.w, fmaf(a_pop, nx.w, a_noop * st[i].w));
        __stcs(&nst4[i * 32 + lane], ns);
        acc = f4fma(e[i] * ginv, ns, acc);
    }
    acc = f4add(acc, f4shflxor(acc, 8));
    acc = f4add(acc, f4shflxor(acc, 16));
    if (g == 0)
        g_mem4[th * 8 + c] = acc;
}

// ---------------------------------------------------------------------------
// Kernel 4: out = (mem @ Wu + bu)*rw + hidden. Block = 128 tok x 1 head.
// tg = tid>>3 (4 tokens), dg = tid&7 (4 d-pairs: d floats 8dg..8dg+7).
// mem tile transposed [sd][tok], XOR swizzle; Wu stored [j][sd][dg].
// ---------------------------------------------------------------------------
__global__ __launch_bounds__(256) void k_out(
    const float* __restrict__ hidden,
    const float* __restrict__ Wu,
    const float* __restrict__ bu,
    const float* __restrict__ res_w,
    float* __restrict__ out)
{
    __shared__ __align__(16) float sMT[32 * 128];   // 16 KB
    __shared__ __align__(16) u64   sWuT[4 * 256];   // 8 KB [j][sd][dg]

    const int tid  = threadIdx.x;
    const int head = blockIdx.x & 15;
    const int tok0 = (blockIdx.x >> 4) * 128;
    const int dg   = tid & 7;
    const int tg   = tid >> 3;

    const u64* Wu2 = (const u64*)Wu;
#pragma unroll
    for (int i = tid; i < 1024; i += 256) {
        int j = i >> 8, sd = (i >> 3) & 31, dgg = i & 7;
        sWuT[i] = Wu2[sd * 32 + dgg * 4 + j];
    }

#pragma unroll
    for (int k = 0; k < 4; k++) {
        int idx = k * 256 + tid;
        int tok = idx >> 3, j2 = idx & 7;
        float4 v = g_mem4[((size_t)(tok0 + tok) * NHEADS + head) * 8 + j2];
        int s0 = j2 * 4;
        const int tq = tok >> 2, tr = tok & 3;
        sMT[(s0 + 0) * 128 + ((tq ^ (s0 + 0)) << 2) + tr] = v.x;
        sMT[(s0 + 1) * 128 + ((tq ^ (s0 + 1)) << 2) + tr] = v.y;
        sMT[(s0 + 2) * 128 + ((tq ^ (s0 + 2)) << 2) + tr] = v.z;
        sMT[(s0 + 3) * 128 + ((tq ^ (s0 + 3)) << 2) + tr] = v.w;
    }
    __syncthreads();

    u64 acc[4][4];
    {
        const u64* bu2 = (const u64*)bu;
#pragma unroll
        for (int j = 0; j < 4; j++) {
            u64 b = __ldg(&bu2[dg * 4 + j]);
            acc[0][j] = b; acc[1][j] = b; acc[2][j] = b; acc[3][j] = b;
        }
    }

#pragma unroll 8
    for (int sd = 0; sd < SD; sd++) {
        float4 a4 = *(const float4*)&sMT[sd * 128 + ((tg ^ sd) << 2)];
        u64 w[4];
#pragma unroll
        for (int j = 0; j < 4; j++) w[j] = sWuT[j * 256 + sd * 8 + dg];
        u64 h0 = pack2(a4.x, a4.x), h1 = pack2(a4.y, a4.y);
        u64 h2 = pack2(a4.z, a4.z), h3 = pack2(a4.w, a4.w);
#pragma unroll
        for (int j = 0; j < 4; j++) {
            fma2(acc[0][j], h0, w[j]);
            fma2(acc[1][j], h1, w[j]);
            fma2(acc[2][j], h2, w[j]);
            fma2(acc[3][j], h3, w[j]);
        }
    }

    const float rw = __ldg(&res_w[0]);
#pragma unroll
    for (int t = 0; t < 4; t++) {
        const int token = tok0 + tg * 4 + t;
        const size_t base = (size_t)token * 256 + head * 16 + dg * 2;
        const float4* hid4 = (const float4*)hidden + base;
        float4* out4 = (float4*)out + base;
        float2 aa = unpack2(acc[t][0]);
        float2 ab = unpack2(acc[t][1]);
        float2 ac = unpack2(acc[t][2]);
        float2 ad = unpack2(acc[t][3]);
        float4 h0 = __ldcs(&hid4[0]);
        float4 h1 = __ldcs(&hid4[1]);
        float4 o0, o1;
        o0.x = fmaf(aa.x, rw, h0.x); o0.y = fmaf(aa.y, rw, h0.y);
        o0.z = fmaf(ab.x, rw, h0.z); o0.w = fmaf(ab.y, rw, h0.w);
        o1.x = fmaf(ac.x, rw, h1.x); o1.y = fmaf(ac.y, rw, h1.y);
        o1.z = fmaf(ad.x, rw, h1.z); o1.w = fmaf(ad.y, rw, h1.w);
        __stcs(&out4[0], o0);
        __stcs(&out4[1], o1);
    }
}

// ---------------------------------------------------------------------------
extern "C" void kernel_launch(void* const* d_in, const int* in_sizes, int n_in,
                              void* d_out, int out_size)
{
    const float* hidden = (const float*)d_in[0];
    const float* stack  = (const float*)d_in[1];
    const float* mask   = (const float*)d_in[2];
    const float* Wa     = (const float*)d_in[3];
    const float* ba     = (const float*)d_in[4];
    const float* Wd     = (const float*)d_in[5];
    const float* bd     = (const float*)d_in[6];
    const float* Wu     = (const float*)d_in[7];
    const float* bu     = (const float*)d_in[8];
    const float* Wg     = (const float*)d_in[9];
    const float* bg     = (const float*)d_in[10];
    const float* res_w  = (const float*)d_in[11];

    float* out       = (float*)d_out;
    float* new_stack = out + (size_t)N_TOKENS * HDIM;
    float* new_mask  = new_stack + (size_t)N_TOKENS * NHEADS * SLOTS * SD;

    (void)in_sizes; (void)n_in; (void)out_size;

    k_waT<<<192, 256>>>(Wa);
    k_actions_part<<<256, 256>>>(hidden);
    k_act_reduce<<<N_TOKENS / 16, 256>>>(ba);
    k_kv<<<(N_TOKENS / 128) * NHEADS, 256>>>(hidden, Wd, bd);
    k_stack<<<N_TOKENS * NHEADS / 8, 256>>>(stack, mask, Wg, bg,
                                            new_stack, new_mask);
    k_out<<<(N_TOKENS / 128) * NHEADS, 256>>>(hidden, Wu, bu, res_w, out);
}